// round 16
// baseline (speedup 1.0000x reference)
#include <cuda_runtime.h>
#include <cuda_bf16.h>
#include <math.h>
#include <stdint.h>

// ---------------- problem constants ----------------
#define BB   4
#define LLEN 4096
#define DD   768
#define KK   12
#define KQ   6
#define HH   64
#define MEM  768          // K*H
#define CHN  1548         // K + 2*FLAT
#define FLAT 768
#define DSW  384
#define DEXP 192
#define LAT  192
#define CKN  4
#define TOK  (BB*LLEN)    // 16384
#define NCH  64           // scan chunks per sequence
#define CLEN 64           // elements per chunk (NCH*CLEN = L)

// packed x-projection layout: [z(780) | q(768) | glin(12) | lat(192)] = 1752
#define PW   1752
#define OFF_Q 780
#define OFF_G 1548
#define OFF_D 1560
#define SPLITC 896        // proj GEMM column split: A = [0,896), B = [896,1752)

// ---------------- device scratch ----------------
__device__ float g_wcatT[PW * DD];       //   5 MB : packed proj weights (tf32), [N,K] K-major
__device__ float g_wupT[4608 * LAT];     //   3.5MB (tf32)
__device__ float g_woutT[DD * 2304];     //   7 MB (tf32)
__device__ __nv_bfloat16 g_bthi[KK * DSW * 128]; // spec B hi, per-head [384,128] K-major
__device__ __nv_bfloat16 g_btlo[KK * DSW * 128]; // spec B lo
__device__ float g_xr[TOK * DD];         //  50 MB : tf32-rounded x
__device__ float g_zq[TOK * PW];         // 114 MB
__device__ float g_merged[TOK * CHN];    // 101 MB
__device__ float g_part[BB * CHN * NCH];
__device__ __nv_bfloat16 g_ohi[TOK * 1536];  // 50 MB : o hi plane
__device__ __nv_bfloat16 g_olo[TOK * 1536];  // 50 MB : o lo plane
__device__ float g_ya[TOK * 2304];       // 151 MB (tf32) : written directly by spec_up
__device__ float g_theta[768];
__device__ float g_slope[KK];

// ---------------- helpers ----------------
__device__ __forceinline__ float softplus_f(float x) {
    return (x > 0.f) ? x + log1pf(expf(-x)) : log1pf(expf(x));
}
__device__ __forceinline__ float sigmoid_f(float x) {
    return 1.f / (1.f + expf(-x));
}
__device__ __forceinline__ uint32_t smem_u32(const void* p) {
    uint32_t a;
    asm("{ .reg .u64 t; cvta.to.shared.u64 t, %1; cvt.u32.u64 %0, t; }" : "=r"(a) : "l"(p));
    return a;
}
__device__ __forceinline__ uint32_t cvt_tf32(float f) {
    uint32_t u;
    asm("cvt.rna.tf32.f32 %0, %1;" : "=r"(u) : "f"(f));
    return u;
}
__device__ __forceinline__ float round_tf32(float f) {
    return __uint_as_float(cvt_tf32(f));
}
__device__ __forceinline__ void ldsm4(uint32_t* r, uint32_t addr) {
    asm volatile("ldmatrix.sync.aligned.m8n8.x4.shared.b16 {%0,%1,%2,%3}, [%4];"
        : "=r"(r[0]), "=r"(r[1]), "=r"(r[2]), "=r"(r[3]) : "r"(addr));
}
__device__ __forceinline__ void mma_tf32(float* d, const uint32_t* a, uint32_t b0, uint32_t b1) {
    asm volatile("mma.sync.aligned.m16n8k8.row.col.f32.tf32.tf32.f32 "
        "{%0,%1,%2,%3}, {%4,%5,%6,%7}, {%8,%9}, {%0,%1,%2,%3};"
        : "+f"(d[0]), "+f"(d[1]), "+f"(d[2]), "+f"(d[3])
        : "r"(a[0]), "r"(a[1]), "r"(a[2]), "r"(a[3]), "r"(b0), "r"(b1));
}
__device__ __forceinline__ void mma_bf16(float* d, const uint32_t* a, uint32_t b0, uint32_t b1) {
    asm volatile("mma.sync.aligned.m16n8k16.row.col.f32.bf16.bf16.f32 "
        "{%0,%1,%2,%3}, {%4,%5,%6,%7}, {%8,%9}, {%0,%1,%2,%3};"
        : "+f"(d[0]), "+f"(d[1]), "+f"(d[2]), "+f"(d[3])
        : "r"(a[0]), "r"(a[1]), "r"(a[2]), "r"(a[3]), "r"(b0), "r"(b1));
}
__device__ __forceinline__ void cp_async16(uint32_t saddr, const void* g, int szbytes) {
    asm volatile("cp.async.cg.shared.global [%0], [%1], 16, %2;"
                 :: "r"(saddr), "l"(g), "r"(szbytes) : "memory");
}
#define CP_COMMIT() asm volatile("cp.async.commit_group;" ::: "memory")
#define CP_WAIT1()  asm volatile("cp.async.wait_group 1;" ::: "memory")
#define CP_WAIT0()  asm volatile("cp.async.wait_group 0;" ::: "memory")

// ---------------- precompute theta/slopes ----------------
__global__ void precomp_kernel(const float* __restrict__ theta_raw,
                               const float* __restrict__ decay_slopes) {
    int i = threadIdx.x;
    if (i < 768) g_theta[i] = softplus_f(theta_raw[i]) + 0.001f;
    if (i < KK)  g_slope[i] = softplus_f(decay_slopes[i]);
}

// ---------------- producers: tf32-round at pack time ----------------
__global__ void round_copy_kernel(const float* __restrict__ src, float* __restrict__ dst, int n4) {
    int i = blockIdx.x * 256 + threadIdx.x;
    if (i >= n4) return;
    float4 v = ((const float4*)src)[i];
    v.x = round_tf32(v.x); v.y = round_tf32(v.y);
    v.z = round_tf32(v.z); v.w = round_tf32(v.w);
    ((float4*)dst)[i] = v;
}
__global__ void pack_wcatT_kernel(const float* __restrict__ Wmem, const float* __restrict__ Wq,
                                  const float* __restrict__ Wg, const float* __restrict__ Wdown) {
    int idx = blockIdx.x * 256 + threadIdx.x;   // idx = c*768 + r
    if (idx >= PW * DD) return;
    int c = idx / DD, r = idx % DD;
    float v;
    if (c < OFF_Q)      v = Wmem[r * 780 + c];
    else if (c < OFF_G) v = Wq[r * 768 + (c - OFF_Q)];
    else if (c < OFF_D) v = Wg[r * KK + (c - OFF_G)];
    else                v = Wdown[r * LAT + (c - OFF_D)];
    g_wcatT[idx] = round_tf32(v);
}
__global__ void transpose_tiled_kernel(const float* __restrict__ W, float* __restrict__ WT,
                                       int Kd, int N) {
    __shared__ float tile[32][33];
    const int kb = blockIdx.x * 32, nb = blockIdx.y * 32;
    const int tx = threadIdx.x, ty = threadIdx.y;
#pragma unroll
    for (int i = 0; i < 32; i += 8)
        tile[ty + i][tx] = W[(size_t)(kb + ty + i) * N + nb + tx];
    __syncthreads();
#pragma unroll
    for (int i = 0; i < 32; i += 8)
        WT[(size_t)(nb + ty + i) * Kd + kb + tx] = round_tf32(tile[tx][ty + i]);
}
__global__ void spec_bt_kernel(const float* __restrict__ Wre, const float* __restrict__ Wim) {
    int idx = blockIdx.x * 256 + threadIdx.x;
    if (idx >= KK * DSW * 128) return;
    int r = idx & 127;
    int n = (idx >> 7) % DSW;
    int z = idx / (DSW * 128);
    float v = (r < 64) ? Wre[((size_t)z * 64 + r) * DSW + n]
                       : Wim[((size_t)z * 64 + r - 64) * DSW + n];
    __nv_bfloat16 hb = __float2bfloat16(v);
    g_bthi[idx] = hb;
    g_btlo[idx] = __float2bfloat16(v - __bfloat162float(hb));
}

// ---------------- tf32 mma GEMM, 3-stage cp.async: C = A @ Bt^T ----------------
#define GEMM_SMEM (3 * 32768)
__global__ __launch_bounds__(256, 2)
void tf32_mma_gemm(const float* __restrict__ A, const float* __restrict__ Bt,
                   float* __restrict__ C, int Ntot, int Kd, int lda, int ldc, int roundFrom) {
    extern __shared__ char sm[];
    const uint32_t sbase = smem_u32(sm);
    const int tid = threadIdx.x;
    const int w = tid >> 5;
    const int l = tid & 31;
    const int rowBase = blockIdx.y * 128;
    const int colBase = blockIdx.x * 128;
    const int warpRow = w >> 1;
    const int warpCol = w & 1;

    float acc[2][8][4];
#pragma unroll
    for (int mt = 0; mt < 2; mt++)
#pragma unroll
        for (int nt = 0; nt < 8; nt++)
#pragma unroll
            for (int i = 0; i < 4; i++) acc[mt][nt][i] = 0.f;

    const int lr4 = w * 4 + (l >> 3);
    const int lcs = (l & 7) * 16;

    auto issue = [&](int ci, int buf) {
        const uint32_t aB = sbase + buf * 32768;
        const uint32_t bB = aB + 16384;
        const float* As = A + (size_t)rowBase * lda + ci * 32 + (lcs >> 2);
        const float* Bs = Bt + ci * 32 + (lcs >> 2);
#pragma unroll
        for (int it = 0; it < 4; it++) {
            int r = it * 32 + lr4;
            int sw = r * 128 + (lcs ^ ((r & 7) << 4));
            cp_async16(aB + sw, As + (size_t)r * lda, 16);
            int n = colBase + r;
            cp_async16(bB + sw, Bs + (size_t)n * Kd, (n < Ntot) ? 16 : 0);
        }
        CP_COMMIT();
    };

    const int lfr = (l & 7) + ((l >> 3) & 1) * 8;
    const int lf16 = (l >> 4) * 16;

    auto compute = [&](int buf) {
        const uint32_t aB = sbase + buf * 32768;
        const uint32_t bB = aB + 16384;
#pragma unroll
        for (int ks = 0; ks < 4; ks++) {
            const int cb = ks * 32 + lf16;
            uint32_t af[2][4];
#pragma unroll
            for (int mt = 0; mt < 2; mt++) {
                int r = warpRow * 32 + mt * 16 + lfr;
                ldsm4(af[mt], aB + r * 128 + (cb ^ ((r & 7) << 4)));
            }
#pragma unroll
            for (int h = 0; h < 2; h++) {
                uint32_t bf[2][4];
#pragma unroll
                for (int j = 0; j < 2; j++) {
                    int nb = h * 2 + j;
                    int r = warpCol * 64 + nb * 16 + lfr;
                    ldsm4(bf[j], bB + r * 128 + (cb ^ ((r & 7) << 4)));
                }
#pragma unroll
                for (int mt = 0; mt < 2; mt++)
#pragma unroll
                    for (int j = 0; j < 2; j++) {
                        int nt = (h * 2 + j) * 2;
                        mma_tf32(acc[mt][nt],     af[mt], bf[j][0], bf[j][2]);
                        mma_tf32(acc[mt][nt + 1], af[mt], bf[j][1], bf[j][3]);
                    }
            }
        }
    };

    const int nc = Kd >> 5;
    issue(0, 0);
    if (nc > 1) issue(1, 1);

    for (int ci = 0; ci < nc; ci++) {
        if (ci + 2 < nc) { CP_WAIT1(); } else { CP_WAIT0(); }
        __syncthreads();
        if (ci + 2 < nc) issue(ci + 2, (ci + 2) % 3);
        compute(ci % 3);
    }

    const int g = l >> 2, tig = l & 3;
#pragma unroll
    for (int mt = 0; mt < 2; mt++)
#pragma unroll
        for (int i = 0; i < 2; i++) {
            int r = rowBase + warpRow * 32 + mt * 16 + g + i * 8;
            float* Crow = C + (size_t)r * ldc;
#pragma unroll
            for (int nt = 0; nt < 8; nt++) {
                int cc = colBase + warpCol * 64 + nt * 8 + tig * 2;
                if (cc < Ntot) {
                    float2 v = make_float2(acc[mt][nt][i * 2], acc[mt][nt][i * 2 + 1]);
                    if (cc >= roundFrom) { v.x = round_tf32(v.x); v.y = round_tf32(v.y); }
                    *(float2*)(Crow + cc) = v;
                }
            }
        }
}

// ---------------- fused W_up + spec + SiLU GEMM ----------------
// CTA covers head z's PAIRED columns: n(u) = bx*64 + u + (u<64 ? 0 : 128).
// Phase A: acc = zq_lat @ WupT^T (tf32, K=192); rescale by hw/gate.
// Phase B: acc += o @ Bt^T (bf16 hi/lo 3-term, K=128). y = gate*acc.
// Epilogue: gate warps stash yg to smem; value warps emit ya = yv*yg*sigmoid(yg).
#define SPEC_SMEM (3 * 32768)
__global__ __launch_bounds__(256, 2)
void spec_up_mma_kernel(const float* __restrict__ bg, const float* __restrict__ hw) {
    extern __shared__ char sm[];
    const uint32_t sbase = smem_u32(sm);
    const int bx = blockIdx.x;              // 0..2
    const int z = blockIdx.z;
    const int tid = threadIdx.x;
    const int w = tid >> 5, l = tid & 31;
    const int rowBase = blockIdx.y * 128;
    const int warpRow = w >> 1, warpCol = w & 1;
    const int g = l >> 2, tig = l & 3;

    float acc[2][8][4];
#pragma unroll
    for (int mt = 0; mt < 2; mt++)
#pragma unroll
        for (int nt = 0; nt < 8; nt++)
#pragma unroll
            for (int i = 0; i < 4; i++) acc[mt][nt][i] = 0.f;

    const int lr4 = w * 4 + (l >> 3);
    const int lcs = (l & 7) * 16;
    const int lfr = (l & 7) + ((l >> 3) & 1) * 8;
    const int lf16 = (l >> 4) * 16;
    const int lhalf = l >> 4;

    auto nmap = [&](int r) { return bx * 64 + r + ((r < 64) ? 0 : 128); };

    // ---------- phase A: tf32 up-GEMM, K=192 (6 chunks) ----------
    const float* Aup = g_zq + OFF_D;
    auto issueA = [&](int ci, int buf) {
        const uint32_t aB = sbase + buf * 32768;
        const uint32_t bB = aB + 16384;
#pragma unroll
        for (int it = 0; it < 4; it++) {
            int r = it * 32 + lr4;
            int sw = r * 128 + (lcs ^ ((r & 7) << 4));
            cp_async16(aB + sw, Aup + (size_t)(rowBase + r) * PW + ci * 32 + (lcs >> 2), 16);
            cp_async16(bB + sw, g_wupT + (size_t)(z * DSW + nmap(r)) * LAT + ci * 32 + (lcs >> 2), 16);
        }
        CP_COMMIT();
    };
    auto computeA = [&](int buf) {
        const uint32_t aB = sbase + buf * 32768;
        const uint32_t bB = aB + 16384;
#pragma unroll
        for (int ks = 0; ks < 4; ks++) {
            const int cb = ks * 32 + lf16;
            uint32_t af[2][4];
#pragma unroll
            for (int mt = 0; mt < 2; mt++) {
                int r = warpRow * 32 + mt * 16 + lfr;
                ldsm4(af[mt], aB + r * 128 + (cb ^ ((r & 7) << 4)));
            }
#pragma unroll
            for (int h = 0; h < 2; h++) {
                uint32_t bf[2][4];
#pragma unroll
                for (int j = 0; j < 2; j++) {
                    int nb = h * 2 + j;
                    int r = warpCol * 64 + nb * 16 + lfr;
                    ldsm4(bf[j], bB + r * 128 + (cb ^ ((r & 7) << 4)));
                }
#pragma unroll
                for (int mt = 0; mt < 2; mt++)
#pragma unroll
                    for (int j = 0; j < 2; j++) {
                        int nt = (h * 2 + j) * 2;
                        mma_tf32(acc[mt][nt],     af[mt], bf[j][0], bf[j][2]);
                        mma_tf32(acc[mt][nt + 1], af[mt], bf[j][1], bf[j][3]);
                    }
            }
        }
    };

    {
        const int nc = LAT / 32;   // 6
        issueA(0, 0);
        issueA(1, 1);
        for (int ci = 0; ci < nc; ci++) {
            if (ci + 2 < nc) { CP_WAIT1(); } else { CP_WAIT0(); }
            __syncthreads();
            if (ci + 2 < nc) issueA(ci + 2, (ci + 2) % 3);
            computeA(ci % 3);
        }
    }
    __syncthreads();

    // ---------- rescale: acc *= hw/gate ----------
    const float hwz = hw[z];
    const float bgz = bg[z];
    float gate[2][2];
#pragma unroll
    for (int mt = 0; mt < 2; mt++)
#pragma unroll
        for (int i = 0; i < 2; i++) {
            int r = rowBase + warpRow * 32 + mt * 16 + g + i * 8;
            gate[mt][i] = sigmoid_f(g_zq[(size_t)r * PW + OFF_G + z] + bgz);
            float f = hwz / gate[mt][i];
#pragma unroll
            for (int nt = 0; nt < 8; nt++) {
                acc[mt][nt][i * 2]     *= f;
                acc[mt][nt][i * 2 + 1] *= f;
            }
        }

    // ---------- phase B: bf16 hi/lo spec GEMM, K=128 (4 chunks) ----------
    auto issueB = [&](int ci, int st) {
        const uint32_t base = sbase + st * 32768;
        const int rr = tid >> 2, seg = tid & 3;
        const int colb = ci * 32 + seg * 8;
#pragma unroll
        for (int half = 0; half < 2; half++) {
            int r = half * 64 + rr;
            uint32_t sa = base + r * 64 + ((seg * 16) ^ ((r & 3) << 4));
            size_t ga = (size_t)(rowBase + r) * 1536 + z * 128 + colb;
            cp_async16(sa,         g_ohi + ga, 16);
            cp_async16(sa + 8192,  g_olo + ga, 16);
            size_t gb = ((size_t)(z * DSW + nmap(r))) * 128 + colb;
            cp_async16(sa + 16384, g_bthi + gb, 16);
            cp_async16(sa + 24576, g_btlo + gb, 16);
        }
        CP_COMMIT();
    };
    auto computeB = [&](int st) {
        const uint32_t base = sbase + st * 32768;
#pragma unroll
        for (int s = 0; s < 2; s++) {
            const int seg = s * 2 + lhalf;
            uint32_t Ah[2][4], Al[2][4];
#pragma unroll
            for (int mt = 0; mt < 2; mt++) {
                int r = warpRow * 32 + mt * 16 + lfr;
                uint32_t off = r * 64 + (((uint32_t)seg * 16) ^ ((r & 3) << 4));
                ldsm4(Ah[mt], base + off);
                ldsm4(Al[mt], base + 8192 + off);
            }
#pragma unroll
            for (int j = 0; j < 4; j++) {
                uint32_t Bh[4], Bl[4];
                int r = warpCol * 64 + j * 16 + lfr;
                uint32_t off = r * 64 + (((uint32_t)seg * 16) ^ ((r & 3) << 4));
                ldsm4(Bh, base + 16384 + off);
                ldsm4(Bl, base + 24576 + off);
#pragma unroll
                for (int mt = 0; mt < 2; mt++) {
                    int nt = j * 2;
                    mma_bf16(acc[mt][nt],     Ah[mt], Bh[0], Bh[2]);
                    mma_bf16(acc[mt][nt],     Al[mt], Bh[0], Bh[2]);
                    mma_bf16(acc[mt][nt],     Ah[mt], Bl[0], Bl[2]);
                    mma_bf16(acc[mt][nt + 1], Ah[mt], Bh[1], Bh[3]);
                    mma_bf16(acc[mt][nt + 1], Al[mt], Bh[1], Bh[3]);
                    mma_bf16(acc[mt][nt + 1], Ah[mt], Bl[1], Bl[3]);
                }
            }
        }
    };

    issueB(0, 0);
    issueB(1, 1);
    for (int ci = 0; ci < 4; ci++) {
        if (ci + 2 < 4) { CP_WAIT1(); } else { CP_WAIT0(); }
        __syncthreads();
        if (ci + 2 < 4) issueB(ci + 2, (ci + 2) % 3);
        computeB(ci % 3);
    }
    __syncthreads();

    // ---------- epilogue: gate warps stash yg; value warps emit ya ----------
    float* ygbuf = (float*)sm;   // [128][65] floats (reuse stage smem)
    if (warpCol == 1) {
#pragma unroll
        for (int mt = 0; mt < 2; mt++)
#pragma unroll
            for (int i = 0; i < 2; i++) {
                int rl = warpRow * 32 + mt * 16 + g + i * 8;
                const float gt = gate[mt][i];
#pragma unroll
                for (int nt = 0; nt < 8; nt++) {
                    int u = nt * 8 + tig * 2;
                    ygbuf[rl * 65 + u]     = acc[mt][nt][i * 2] * gt;
                    ygbuf[rl * 65 + u + 1] = acc[mt][nt][i * 2 + 1] * gt;
                }
            }
    }
    __syncthreads();
    if (warpCol == 0) {
#pragma unroll
        for (int mt = 0; mt < 2; mt++)
#pragma unroll
            for (int i = 0; i < 2; i++) {
                int rl = warpRow * 32 + mt * 16 + g + i * 8;
                int r = rowBase + rl;
                const float gt = gate[mt][i];
                float* Yrow = g_ya + (size_t)r * 2304 + z * DEXP + bx * 64;
#pragma unroll
                for (int nt = 0; nt < 8; nt++) {
                    int u = nt * 8 + tig * 2;
                    float yv0 = acc[mt][nt][i * 2] * gt;
                    float yv1 = acc[mt][nt][i * 2 + 1] * gt;
                    float yg0 = ygbuf[rl * 65 + u];
                    float yg1 = ygbuf[rl * 65 + u + 1];
                    float2 v;
                    v.x = round_tf32(yv0 * yg0 * sigmoid_f(yg0));
                    v.y = round_tf32(yv1 * yg1 * sigmoid_f(yg1));
                    *(float2*)(Yrow + u) = v;
                }
            }
    }
}

// ---------------- fused merged construction + chunk sums ----------------
// grid (NCH, BB, 3), 256 threads; chunk length CLEN=64.
__global__ __launch_bounds__(256)
void build_scan1_kernel(const float* __restrict__ ck,
                        const float* __restrict__ score_scale) {
    const int ch = blockIdx.x;
    const int b  = blockIdx.y;
    const int cs = blockIdx.z;
    const int tid = threadIdx.x;
    __shared__ float spw[KK][CLEN];
    const int l0 = ch * CLEN;
    const int t0 = b * LLEN + l0;

    // phase 1: threads 0..CLEN-1 compute pw for all 12 heads at their token
    if (tid < CLEN) {
        const int i = tid;
        const int l = l0 + i;
        const int t = t0 + i;
#pragma unroll
        for (int k = 0; k < KK; k++) {
            float s = 0.f;
#pragma unroll
            for (int j = 0; j < CKN; j++) {
                int ll = l - (CKN - 1) + j;
                if (ll >= 0)
                    s += g_zq[(size_t)(t - (CKN - 1) + j) * PW + MEM + k] * ck[j * 780 + MEM + k];
            }
            float lp = fminf(fmaxf(score_scale[k] * s, -20.f), 20.f);
            float pw = expf(lp - g_slope[k] * (float)(LLEN - 1 - l));
            spw[k][i] = pw;
            if (cs == 0) g_merged[(size_t)t * CHN + k] = pw;
        }
    }
    __syncthreads();
    if (cs == 0 && tid < KK) {
        float s = 0.f;
        for (int i = 0; i < CLEN; i++) s += spw[tid][i];
        g_part[(b * CHN + tid) * NCH + ch] = s;
    }

    // phase 2: kv channel c, rolling 4-tap window over CLEN tokens
    const int c = cs * 256 + tid;
    const int k = c >> 6;
    const float w0 = ck[0 * 780 + c], w1 = ck[1 * 780 + c];
    const float w2 = ck[2 * 780 + c], w3 = ck[3 * 780 + c];
    const float th = g_theta[c];
    float z0 = 0.f, z1 = 0.f, z2 = 0.f;
    if (l0 >= 3) {
        z0 = g_zq[(size_t)(t0 - 3) * PW + c];
        z1 = g_zq[(size_t)(t0 - 2) * PW + c];
        z2 = g_zq[(size_t)(t0 - 1) * PW + c];
    }
    float sum_re = 0.f, sum_im = 0.f;
    for (int i = 0; i < CLEN; i++) {
        const size_t t = (size_t)(t0 + i);
        float z3 = g_zq[t * PW + c];
        float kv = w0 * z0 + w1 * z1 + w2 * z2 + w3 * z3;
        float phi = tanhf(kv) * th;
        float sn, cn;
        sincosf(phi, &sn, &cn);
        float wgt = kv * spw[k][i];
        float re = wgt * cn, im = wgt * sn;
        g_merged[t * CHN + KK + c] = re;
        g_merged[t * CHN + KK + FLAT + c] = im;
        sum_re += re;
        sum_im += im;
        z0 = z1; z1 = z2; z2 = z3;
    }
    g_part[(b * CHN + KK + c) * NCH + ch] = sum_re;
    g_part[(b * CHN + KK + FLAT + c) * NCH + ch] = sum_im;
}

// ---------------- pass2: exclusive prefix over chunk sums ----------------
__global__ void scan_pass2() {
    int idx = blockIdx.x * 256 + threadIdx.x;
    if (idx >= BB * CHN) return;
    int base = idx * NCH;
    float off = 0.f;
#pragma unroll
    for (int i = 0; i < NCH; i++) {
        float v = g_part[base + i];
        g_part[base + i] = off;
        off += v;
    }
}

// ---------------- fused pass3 + combine: cumsum (registers) -> o (bf16 hi/lo) ----------------
// grid (NCH, BB, KK), 64 threads; chunk length CLEN=64, 1 den value/thread.
__global__ __launch_bounds__(64)
void scan3_combine_kernel(const float* __restrict__ norm_scale) {
    const int ch = blockIdx.x;
    const int b  = blockIdx.y;
    const int k  = blockIdx.z;
    const int l  = threadIdx.x;    // 0..63
    __shared__ float sinv[CLEN];
    __shared__ float wsum;
    const int t0 = b * LLEN + ch * CLEN;

    // inclusive scan of den over 64 tokens (1/thread, 2 warps)
    float v = g_merged[(size_t)(t0 + l) * CHN + k];
    float s = v;
#pragma unroll
    for (int d = 1; d < 32; d <<= 1) {
        float t = __shfl_up_sync(0xFFFFFFFFu, s, d);
        if ((l & 31) >= d) s += t;
    }
    if (l == 31) wsum = s;
    __syncthreads();
    float incl = g_part[(b * CHN + k) * NCH + ch] + s + ((l >= 32) ? wsum : 0.f);
    sinv[l] = 1.f / fmaxf(incl, 1e-4f);
    __syncthreads();

    const int hh = l;
    const int cre = KK + k * 64 + hh;
    const int cim = KK + FLAT + k * 64 + hh;
    float run_re = g_part[(b * CHN + cre) * NCH + ch];
    float run_im = g_part[(b * CHN + cim) * NCH + ch];
    const float ns = norm_scale[k * 64 + hh];
    const int kq = k >> 1;

#pragma unroll 4
    for (int i = 0; i < CLEN; i++) {
        const size_t t = (size_t)(t0 + i);
        run_re += g_merged[t * CHN + cre];
        run_im += g_merged[t * CHN + cim];
        float iv = sinv[i];
        float sre = run_re * iv;
        float sim = run_im * iv;
        float2 q2 = *(const float2*)(g_zq + t * PW + OFF_Q + kq * 128 + 2 * hh);
        float vre = (sre * q2.x + sim * q2.y) * ns;
        float vim = (sim * q2.x - sre * q2.y) * ns;
        size_t oidx = t * 1536 + k * 128 + hh;
        __nv_bfloat16 hb;
        hb = __float2bfloat16(vre);
        g_ohi[oidx] = hb;
        g_olo[oidx] = __float2bfloat16(vre - __bfloat162float(hb));
        hb = __float2bfloat16(vim);
        g_ohi[oidx + 64] = hb;
        g_olo[oidx + 64] = __float2bfloat16(vim - __bfloat162float(hb));
    }
}

// ---------------- host ----------------
static float* sym_addr(const void* sym) {
    void* p = nullptr;
    cudaGetSymbolAddress(&p, sym);
    return (float*)p;
}

extern "C" void kernel_launch(void* const* d_in, const int* in_sizes, int n_in,
                              void* d_out, int out_size) {
    const float* x        = (const float*)d_in[0];
    const float* W_mem    = (const float*)d_in[1];
    const float* conv_k   = (const float*)d_in[2];
    const float* W_q      = (const float*)d_in[3];
    const float* th_raw   = (const float*)d_in[4];
    const float* d_slopes = (const float*)d_in[5];
    const float* sc_scale = (const float*)d_in[6];
    const float* W_re     = (const float*)d_in[7];
    const float* W_im     = (const float*)d_in[8];
    const float* n_scale  = (const float*)d_in[9];
    const float* Wg       = (const float*)d_in[10];
    const float* bg       = (const float*)d_in[11];
    const float* W_down   = (const float*)d_in[12];
    const float* W_up     = (const float*)d_in[13];
    const float* hw       = (const float*)d_in[14];
    const float* W_out    = (const float*)d_in[15];
    float* out = (float*)d_out;

    float* pwcatT = sym_addr(g_wcatT);
    float* pwupT  = sym_addr(g_wupT);
    float* pwoutT = sym_addr(g_woutT);
    float* pxr    = sym_addr(g_xr);
    float* pzq    = sym_addr(g_zq);
    float* pya    = sym_addr(g_ya);

    static cudaStream_t s1;
    static cudaEvent_t evA, evC, evW, evP, evB;
    static int init_done = 0;
    if (!init_done) {
        cudaFuncSetAttribute(tf32_mma_gemm, cudaFuncAttributeMaxDynamicSharedMemorySize, GEMM_SMEM);
        cudaFuncSetAttribute(spec_up_mma_kernel, cudaFuncAttributeMaxDynamicSharedMemorySize, SPEC_SMEM);
        cudaStreamCreateWithFlags(&s1, cudaStreamNonBlocking);
        cudaEventCreateWithFlags(&evA, cudaEventDisableTiming);
        cudaEventCreateWithFlags(&evC, cudaEventDisableTiming);
        cudaEventCreateWithFlags(&evW, cudaEventDisableTiming);
        cudaEventCreateWithFlags(&evP, cudaEventDisableTiming);
        cudaEventCreateWithFlags(&evB, cudaEventDisableTiming);
        init_done = 1;
    }

    dim3 blk(256);
    const int MB = TOK / 128;   // 128 row-blocks
    const int NOROUND = 1 << 30;

    // ---- fork side stream: pack (needed by proj) first, then the rest of the prep ----
    cudaEventRecord(evA, 0);
    cudaStreamWaitEvent(s1, evA, 0);
    pack_wcatT_kernel<<<(PW * DD + 255) / 256, blk, 0, s1>>>(W_mem, W_q, Wg, W_down);
    cudaEventRecord(evW, s1);
    precomp_kernel<<<1, 768, 0, s1>>>(th_raw, d_slopes);
    transpose_tiled_kernel<<<dim3(LAT / 32, 4608 / 32), dim3(32, 8), 0, s1>>>(W_up, pwupT, LAT, 4608);
    transpose_tiled_kernel<<<dim3(2304 / 32, DD / 32), dim3(32, 8), 0, s1>>>(W_out, pwoutT, 2304, DD);
    spec_bt_kernel<<<(KK * DSW * 128 + 255) / 256, blk, 0, s1>>>(W_re, W_im);
    cudaEventRecord(evC, s1);

    // ---- main: x rounding (overlaps pack), then proj part A (cols 0..895: z + score) ----
    round_copy_kernel<<<(TOK * DD / 4 + 255) / 256, blk>>>(x, pxr, TOK * DD / 4);
    cudaStreamWaitEvent(0, evW, 0);
    tf32_mma_gemm<<<dim3(SPLITC / 128, MB), blk, GEMM_SMEM>>>(pxr, pwcatT, pzq, SPLITC, DD, DD, PW, NOROUND);
    cudaEventRecord(evP, 0);

    // ---- side: proj part B (cols 896..1751: q + glin + lat), overlaps the scan chain ----
    cudaStreamWaitEvent(s1, evP, 0);
    tf32_mma_gemm<<<dim3((PW - SPLITC + 127) / 128, MB), blk, GEMM_SMEM, s1>>>(
        pxr, pwcatT + (size_t)SPLITC * DD, pzq + SPLITC, PW - SPLITC, DD, DD, PW, OFF_D - SPLITC);
    cudaEventRecord(evB, s1);

    // ---- main: fused merged+pass1, pass2 (needs precomp + proj A only) ----
    cudaStreamWaitEvent(0, evC, 0);
    build_scan1_kernel<<<dim3(NCH, BB, 3), blk>>>(conv_k, sc_scale);
    {
        int n2 = BB * CHN;
        scan_pass2<<<(n2 + 255) / 256, blk>>>();
    }

    // ---- scan3 needs q columns (proj B) ----
    cudaStreamWaitEvent(0, evB, 0);
    scan3_combine_kernel<<<dim3(NCH, BB, KK), 64>>>(n_scale);

    // ---- fused up+spec+silu GEMM -> ya ----
    spec_up_mma_kernel<<<dim3(3, MB, KK), blk, SPEC_SMEM>>>(bg, hw);

    // ---- final projection ----
    tf32_mma_gemm<<<dim3(6, MB), blk, GEMM_SMEM>>>(pya, pwoutT, out, DD, 2304, 2304, DD, NOROUND);
}

// round 17
// speedup vs baseline: 1.0365x; 1.0365x over previous
#include <cuda_runtime.h>
#include <cuda_bf16.h>
#include <math.h>
#include <stdint.h>

// ---------------- problem constants ----------------
#define BB   4
#define LLEN 4096
#define DD   768
#define KK   12
#define KQ   6
#define HH   64
#define MEM  768          // K*H
#define CHN  1548         // K + 2*FLAT
#define FLAT 768
#define DSW  384
#define DEXP 192
#define LAT  192
#define CKN  4
#define TOK  (BB*LLEN)    // 16384
#define NCH  64           // scan chunks per sequence
#define CLEN 64           // elements per chunk (NCH*CLEN = L)

// packed x-projection layout: [z(780) | q(768) | glin(12) | lat(192)] = 1752
#define PW   1752
#define OFF_Q 780
#define OFF_G 1548
#define OFF_D 1560

// ---------------- device scratch ----------------
__device__ float g_wcatT[PW * DD];       //   5 MB : packed proj weights (tf32), [N,K] K-major
__device__ float g_wupT[4608 * LAT];     //   3.5MB (tf32)
__device__ float g_woutT[DD * 2304];     //   7 MB (tf32)
__device__ __nv_bfloat16 g_bthi[KK * DSW * 128]; // spec B hi, per-head [384,128] K-major
__device__ __nv_bfloat16 g_btlo[KK * DSW * 128]; // spec B lo
__device__ float g_xr[TOK * DD];         //  50 MB : tf32-rounded x
__device__ float g_zq[TOK * PW];         // 114 MB
__device__ float g_merged[TOK * CHN];    // 101 MB
__device__ float g_part[BB * CHN * NCH];
__device__ __nv_bfloat16 g_ohi[TOK * 1536];  // 50 MB : o hi plane
__device__ __nv_bfloat16 g_olo[TOK * 1536];  // 50 MB : o lo plane
__device__ float g_ya[TOK * 2304];       // 151 MB (tf32) : written directly by spec_up
__device__ float g_theta[768];
__device__ float g_slope[KK];

// ---------------- helpers ----------------
__device__ __forceinline__ float softplus_f(float x) {
    return (x > 0.f) ? x + log1pf(expf(-x)) : log1pf(expf(x));
}
__device__ __forceinline__ float sigmoid_f(float x) {
    return 1.f / (1.f + expf(-x));
}
__device__ __forceinline__ uint32_t smem_u32(const void* p) {
    uint32_t a;
    asm("{ .reg .u64 t; cvta.to.shared.u64 t, %1; cvt.u32.u64 %0, t; }" : "=r"(a) : "l"(p));
    return a;
}
__device__ __forceinline__ uint32_t cvt_tf32(float f) {
    uint32_t u;
    asm("cvt.rna.tf32.f32 %0, %1;" : "=r"(u) : "f"(f));
    return u;
}
__device__ __forceinline__ float round_tf32(float f) {
    return __uint_as_float(cvt_tf32(f));
}
__device__ __forceinline__ void ldsm4(uint32_t* r, uint32_t addr) {
    asm volatile("ldmatrix.sync.aligned.m8n8.x4.shared.b16 {%0,%1,%2,%3}, [%4];"
        : "=r"(r[0]), "=r"(r[1]), "=r"(r[2]), "=r"(r[3]) : "r"(addr));
}
__device__ __forceinline__ void mma_tf32(float* d, const uint32_t* a, uint32_t b0, uint32_t b1) {
    asm volatile("mma.sync.aligned.m16n8k8.row.col.f32.tf32.tf32.f32 "
        "{%0,%1,%2,%3}, {%4,%5,%6,%7}, {%8,%9}, {%0,%1,%2,%3};"
        : "+f"(d[0]), "+f"(d[1]), "+f"(d[2]), "+f"(d[3])
        : "r"(a[0]), "r"(a[1]), "r"(a[2]), "r"(a[3]), "r"(b0), "r"(b1));
}
__device__ __forceinline__ void mma_bf16(float* d, const uint32_t* a, uint32_t b0, uint32_t b1) {
    asm volatile("mma.sync.aligned.m16n8k16.row.col.f32.bf16.bf16.f32 "
        "{%0,%1,%2,%3}, {%4,%5,%6,%7}, {%8,%9}, {%0,%1,%2,%3};"
        : "+f"(d[0]), "+f"(d[1]), "+f"(d[2]), "+f"(d[3])
        : "r"(a[0]), "r"(a[1]), "r"(a[2]), "r"(a[3]), "r"(b0), "r"(b1));
}
__device__ __forceinline__ void cp_async16(uint32_t saddr, const void* g, int szbytes) {
    asm volatile("cp.async.cg.shared.global [%0], [%1], 16, %2;"
                 :: "r"(saddr), "l"(g), "r"(szbytes) : "memory");
}
#define CP_COMMIT() asm volatile("cp.async.commit_group;" ::: "memory")
#define CP_WAIT1()  asm volatile("cp.async.wait_group 1;" ::: "memory")
#define CP_WAIT0()  asm volatile("cp.async.wait_group 0;" ::: "memory")

// ---------------- precompute theta/slopes ----------------
__global__ void precomp_kernel(const float* __restrict__ theta_raw,
                               const float* __restrict__ decay_slopes) {
    int i = threadIdx.x;
    if (i < 768) g_theta[i] = softplus_f(theta_raw[i]) + 0.001f;
    if (i < KK)  g_slope[i] = softplus_f(decay_slopes[i]);
}

// ---------------- producers: tf32-round at pack time ----------------
__global__ void round_copy_kernel(const float* __restrict__ src, float* __restrict__ dst, int n4) {
    int i = blockIdx.x * 256 + threadIdx.x;
    if (i >= n4) return;
    float4 v = ((const float4*)src)[i];
    v.x = round_tf32(v.x); v.y = round_tf32(v.y);
    v.z = round_tf32(v.z); v.w = round_tf32(v.w);
    ((float4*)dst)[i] = v;
}
__global__ void pack_wcatT_kernel(const float* __restrict__ Wmem, const float* __restrict__ Wq,
                                  const float* __restrict__ Wg, const float* __restrict__ Wdown) {
    int idx = blockIdx.x * 256 + threadIdx.x;   // idx = c*768 + r
    if (idx >= PW * DD) return;
    int c = idx / DD, r = idx % DD;
    float v;
    if (c < OFF_Q)      v = Wmem[r * 780 + c];
    else if (c < OFF_G) v = Wq[r * 768 + (c - OFF_Q)];
    else if (c < OFF_D) v = Wg[r * KK + (c - OFF_G)];
    else                v = Wdown[r * LAT + (c - OFF_D)];
    g_wcatT[idx] = round_tf32(v);
}
__global__ void transpose_tiled_kernel(const float* __restrict__ W, float* __restrict__ WT,
                                       int Kd, int N) {
    __shared__ float tile[32][33];
    const int kb = blockIdx.x * 32, nb = blockIdx.y * 32;
    const int tx = threadIdx.x, ty = threadIdx.y;
#pragma unroll
    for (int i = 0; i < 32; i += 8)
        tile[ty + i][tx] = W[(size_t)(kb + ty + i) * N + nb + tx];
    __syncthreads();
#pragma unroll
    for (int i = 0; i < 32; i += 8)
        WT[(size_t)(nb + ty + i) * Kd + kb + tx] = round_tf32(tile[tx][ty + i]);
}
__global__ void spec_bt_kernel(const float* __restrict__ Wre, const float* __restrict__ Wim) {
    int idx = blockIdx.x * 256 + threadIdx.x;
    if (idx >= KK * DSW * 128) return;
    int r = idx & 127;
    int n = (idx >> 7) % DSW;
    int z = idx / (DSW * 128);
    float v = (r < 64) ? Wre[((size_t)z * 64 + r) * DSW + n]
                       : Wim[((size_t)z * 64 + r - 64) * DSW + n];
    __nv_bfloat16 hb = __float2bfloat16(v);
    g_bthi[idx] = hb;
    g_btlo[idx] = __float2bfloat16(v - __bfloat162float(hb));
}

// ---------------- tf32 mma GEMM, 3-stage cp.async: C = A @ Bt^T ----------------
#define GEMM_SMEM (3 * 32768)
__global__ __launch_bounds__(256, 2)
void tf32_mma_gemm(const float* __restrict__ A, const float* __restrict__ Bt,
                   float* __restrict__ C, int Ntot, int Kd, int lda, int ldc, int roundFrom) {
    extern __shared__ char sm[];
    const uint32_t sbase = smem_u32(sm);
    const int tid = threadIdx.x;
    const int w = tid >> 5;
    const int l = tid & 31;
    const int rowBase = blockIdx.y * 128;
    const int colBase = blockIdx.x * 128;
    const int warpRow = w >> 1;
    const int warpCol = w & 1;

    float acc[2][8][4];
#pragma unroll
    for (int mt = 0; mt < 2; mt++)
#pragma unroll
        for (int nt = 0; nt < 8; nt++)
#pragma unroll
            for (int i = 0; i < 4; i++) acc[mt][nt][i] = 0.f;

    const int lr4 = w * 4 + (l >> 3);
    const int lcs = (l & 7) * 16;

    auto issue = [&](int ci, int buf) {
        const uint32_t aB = sbase + buf * 32768;
        const uint32_t bB = aB + 16384;
        const float* As = A + (size_t)rowBase * lda + ci * 32 + (lcs >> 2);
        const float* Bs = Bt + ci * 32 + (lcs >> 2);
#pragma unroll
        for (int it = 0; it < 4; it++) {
            int r = it * 32 + lr4;
            int sw = r * 128 + (lcs ^ ((r & 7) << 4));
            cp_async16(aB + sw, As + (size_t)r * lda, 16);
            int n = colBase + r;
            cp_async16(bB + sw, Bs + (size_t)n * Kd, (n < Ntot) ? 16 : 0);
        }
        CP_COMMIT();
    };

    const int lfr = (l & 7) + ((l >> 3) & 1) * 8;
    const int lf16 = (l >> 4) * 16;

    auto compute = [&](int buf) {
        const uint32_t aB = sbase + buf * 32768;
        const uint32_t bB = aB + 16384;
#pragma unroll
        for (int ks = 0; ks < 4; ks++) {
            const int cb = ks * 32 + lf16;
            uint32_t af[2][4];
#pragma unroll
            for (int mt = 0; mt < 2; mt++) {
                int r = warpRow * 32 + mt * 16 + lfr;
                ldsm4(af[mt], aB + r * 128 + (cb ^ ((r & 7) << 4)));
            }
#pragma unroll
            for (int h = 0; h < 2; h++) {
                uint32_t bf[2][4];
#pragma unroll
                for (int j = 0; j < 2; j++) {
                    int nb = h * 2 + j;
                    int r = warpCol * 64 + nb * 16 + lfr;
                    ldsm4(bf[j], bB + r * 128 + (cb ^ ((r & 7) << 4)));
                }
#pragma unroll
                for (int mt = 0; mt < 2; mt++)
#pragma unroll
                    for (int j = 0; j < 2; j++) {
                        int nt = (h * 2 + j) * 2;
                        mma_tf32(acc[mt][nt],     af[mt], bf[j][0], bf[j][2]);
                        mma_tf32(acc[mt][nt + 1], af[mt], bf[j][1], bf[j][3]);
                    }
            }
        }
    };

    const int nc = Kd >> 5;
    issue(0, 0);
    if (nc > 1) issue(1, 1);

    for (int ci = 0; ci < nc; ci++) {
        if (ci + 2 < nc) { CP_WAIT1(); } else { CP_WAIT0(); }
        __syncthreads();
        if (ci + 2 < nc) issue(ci + 2, (ci + 2) % 3);
        compute(ci % 3);
    }

    const int g = l >> 2, tig = l & 3;
#pragma unroll
    for (int mt = 0; mt < 2; mt++)
#pragma unroll
        for (int i = 0; i < 2; i++) {
            int r = rowBase + warpRow * 32 + mt * 16 + g + i * 8;
            float* Crow = C + (size_t)r * ldc;
#pragma unroll
            for (int nt = 0; nt < 8; nt++) {
                int cc = colBase + warpCol * 64 + nt * 8 + tig * 2;
                if (cc < Ntot) {
                    float2 v = make_float2(acc[mt][nt][i * 2], acc[mt][nt][i * 2 + 1]);
                    if (cc >= roundFrom) { v.x = round_tf32(v.x); v.y = round_tf32(v.y); }
                    *(float2*)(Crow + cc) = v;
                }
            }
        }
}

// ---------------- fused W_up + spec + SiLU GEMM ----------------
// CTA covers head z's PAIRED columns: n(u) = bx*64 + u + (u<64 ? 0 : 128).
// Phase A: acc = zq_lat @ WupT^T (tf32, K=192); rescale by hw/gate.
// Phase B: acc += o @ Bt^T (bf16 hi/lo 3-term, K=128). y = gate*acc.
// Epilogue: gate warps stash yg to smem; value warps emit ya = yv*yg*sigmoid(yg).
#define SPEC_SMEM (3 * 32768)
__global__ __launch_bounds__(256, 2)
void spec_up_mma_kernel(const float* __restrict__ bg, const float* __restrict__ hw) {
    extern __shared__ char sm[];
    const uint32_t sbase = smem_u32(sm);
    const int bx = blockIdx.x;              // 0..2
    const int z = blockIdx.z;
    const int tid = threadIdx.x;
    const int w = tid >> 5, l = tid & 31;
    const int rowBase = blockIdx.y * 128;
    const int warpRow = w >> 1, warpCol = w & 1;
    const int g = l >> 2, tig = l & 3;

    float acc[2][8][4];
#pragma unroll
    for (int mt = 0; mt < 2; mt++)
#pragma unroll
        for (int nt = 0; nt < 8; nt++)
#pragma unroll
            for (int i = 0; i < 4; i++) acc[mt][nt][i] = 0.f;

    const int lr4 = w * 4 + (l >> 3);
    const int lcs = (l & 7) * 16;
    const int lfr = (l & 7) + ((l >> 3) & 1) * 8;
    const int lf16 = (l >> 4) * 16;
    const int lhalf = l >> 4;

    auto nmap = [&](int r) { return bx * 64 + r + ((r < 64) ? 0 : 128); };

    // ---------- phase A: tf32 up-GEMM, K=192 (6 chunks) ----------
    const float* Aup = g_zq + OFF_D;
    auto issueA = [&](int ci, int buf) {
        const uint32_t aB = sbase + buf * 32768;
        const uint32_t bB = aB + 16384;
#pragma unroll
        for (int it = 0; it < 4; it++) {
            int r = it * 32 + lr4;
            int sw = r * 128 + (lcs ^ ((r & 7) << 4));
            cp_async16(aB + sw, Aup + (size_t)(rowBase + r) * PW + ci * 32 + (lcs >> 2), 16);
            cp_async16(bB + sw, g_wupT + (size_t)(z * DSW + nmap(r)) * LAT + ci * 32 + (lcs >> 2), 16);
        }
        CP_COMMIT();
    };
    auto computeA = [&](int buf) {
        const uint32_t aB = sbase + buf * 32768;
        const uint32_t bB = aB + 16384;
#pragma unroll
        for (int ks = 0; ks < 4; ks++) {
            const int cb = ks * 32 + lf16;
            uint32_t af[2][4];
#pragma unroll
            for (int mt = 0; mt < 2; mt++) {
                int r = warpRow * 32 + mt * 16 + lfr;
                ldsm4(af[mt], aB + r * 128 + (cb ^ ((r & 7) << 4)));
            }
#pragma unroll
            for (int h = 0; h < 2; h++) {
                uint32_t bf[2][4];
#pragma unroll
                for (int j = 0; j < 2; j++) {
                    int nb = h * 2 + j;
                    int r = warpCol * 64 + nb * 16 + lfr;
                    ldsm4(bf[j], bB + r * 128 + (cb ^ ((r & 7) << 4)));
                }
#pragma unroll
                for (int mt = 0; mt < 2; mt++)
#pragma unroll
                    for (int j = 0; j < 2; j++) {
                        int nt = (h * 2 + j) * 2;
                        mma_tf32(acc[mt][nt],     af[mt], bf[j][0], bf[j][2]);
                        mma_tf32(acc[mt][nt + 1], af[mt], bf[j][1], bf[j][3]);
                    }
            }
        }
    };

    {
        const int nc = LAT / 32;   // 6
        issueA(0, 0);
        issueA(1, 1);
        for (int ci = 0; ci < nc; ci++) {
            if (ci + 2 < nc) { CP_WAIT1(); } else { CP_WAIT0(); }
            __syncthreads();
            if (ci + 2 < nc) issueA(ci + 2, (ci + 2) % 3);
            computeA(ci % 3);
        }
    }
    __syncthreads();

    // ---------- rescale: acc *= hw/gate ----------
    const float hwz = hw[z];
    const float bgz = bg[z];
    float gate[2][2];
#pragma unroll
    for (int mt = 0; mt < 2; mt++)
#pragma unroll
        for (int i = 0; i < 2; i++) {
            int r = rowBase + warpRow * 32 + mt * 16 + g + i * 8;
            gate[mt][i] = sigmoid_f(g_zq[(size_t)r * PW + OFF_G + z] + bgz);
            float f = hwz / gate[mt][i];
#pragma unroll
            for (int nt = 0; nt < 8; nt++) {
                acc[mt][nt][i * 2]     *= f;
                acc[mt][nt][i * 2 + 1] *= f;
            }
        }

    // ---------- phase B: bf16 hi/lo spec GEMM, K=128 (4 chunks) ----------
    auto issueB = [&](int ci, int st) {
        const uint32_t base = sbase + st * 32768;
        const int rr = tid >> 2, seg = tid & 3;
        const int colb = ci * 32 + seg * 8;
#pragma unroll
        for (int half = 0; half < 2; half++) {
            int r = half * 64 + rr;
            uint32_t sa = base + r * 64 + ((seg * 16) ^ ((r & 3) << 4));
            size_t ga = (size_t)(rowBase + r) * 1536 + z * 128 + colb;
            cp_async16(sa,         g_ohi + ga, 16);
            cp_async16(sa + 8192,  g_olo + ga, 16);
            size_t gb = ((size_t)(z * DSW + nmap(r))) * 128 + colb;
            cp_async16(sa + 16384, g_bthi + gb, 16);
            cp_async16(sa + 24576, g_btlo + gb, 16);
        }
        CP_COMMIT();
    };
    auto computeB = [&](int st) {
        const uint32_t base = sbase + st * 32768;
#pragma unroll
        for (int s = 0; s < 2; s++) {
            const int seg = s * 2 + lhalf;
            uint32_t Ah[2][4], Al[2][4];
#pragma unroll
            for (int mt = 0; mt < 2; mt++) {
                int r = warpRow * 32 + mt * 16 + lfr;
                uint32_t off = r * 64 + (((uint32_t)seg * 16) ^ ((r & 3) << 4));
                ldsm4(Ah[mt], base + off);
                ldsm4(Al[mt], base + 8192 + off);
            }
#pragma unroll
            for (int j = 0; j < 4; j++) {
                uint32_t Bh[4], Bl[4];
                int r = warpCol * 64 + j * 16 + lfr;
                uint32_t off = r * 64 + (((uint32_t)seg * 16) ^ ((r & 3) << 4));
                ldsm4(Bh, base + 16384 + off);
                ldsm4(Bl, base + 24576 + off);
#pragma unroll
                for (int mt = 0; mt < 2; mt++) {
                    int nt = j * 2;
                    mma_bf16(acc[mt][nt],     Ah[mt], Bh[0], Bh[2]);
                    mma_bf16(acc[mt][nt],     Al[mt], Bh[0], Bh[2]);
                    mma_bf16(acc[mt][nt],     Ah[mt], Bl[0], Bl[2]);
                    mma_bf16(acc[mt][nt + 1], Ah[mt], Bh[1], Bh[3]);
                    mma_bf16(acc[mt][nt + 1], Al[mt], Bh[1], Bh[3]);
                    mma_bf16(acc[mt][nt + 1], Ah[mt], Bl[1], Bl[3]);
                }
            }
        }
    };

    issueB(0, 0);
    issueB(1, 1);
    for (int ci = 0; ci < 4; ci++) {
        if (ci + 2 < 4) { CP_WAIT1(); } else { CP_WAIT0(); }
        __syncthreads();
        if (ci + 2 < 4) issueB(ci + 2, (ci + 2) % 3);
        computeB(ci % 3);
    }
    __syncthreads();

    // ---------- epilogue: gate warps stash yg; value warps emit ya ----------
    float* ygbuf = (float*)sm;   // [128][65] floats (reuse stage smem)
    if (warpCol == 1) {
#pragma unroll
        for (int mt = 0; mt < 2; mt++)
#pragma unroll
            for (int i = 0; i < 2; i++) {
                int rl = warpRow * 32 + mt * 16 + g + i * 8;
                const float gt = gate[mt][i];
#pragma unroll
                for (int nt = 0; nt < 8; nt++) {
                    int u = nt * 8 + tig * 2;
                    ygbuf[rl * 65 + u]     = acc[mt][nt][i * 2] * gt;
                    ygbuf[rl * 65 + u + 1] = acc[mt][nt][i * 2 + 1] * gt;
                }
            }
    }
    __syncthreads();
    if (warpCol == 0) {
#pragma unroll
        for (int mt = 0; mt < 2; mt++)
#pragma unroll
            for (int i = 0; i < 2; i++) {
                int rl = warpRow * 32 + mt * 16 + g + i * 8;
                int r = rowBase + rl;
                const float gt = gate[mt][i];
                float* Yrow = g_ya + (size_t)r * 2304 + z * DEXP + bx * 64;
#pragma unroll
                for (int nt = 0; nt < 8; nt++) {
                    int u = nt * 8 + tig * 2;
                    float yv0 = acc[mt][nt][i * 2] * gt;
                    float yv1 = acc[mt][nt][i * 2 + 1] * gt;
                    float yg0 = ygbuf[rl * 65 + u];
                    float yg1 = ygbuf[rl * 65 + u + 1];
                    float2 v;
                    v.x = round_tf32(yv0 * yg0 * sigmoid_f(yg0));
                    v.y = round_tf32(yv1 * yg1 * sigmoid_f(yg1));
                    *(float2*)(Yrow + u) = v;
                }
            }
    }
}

// ---------------- fused merged construction + chunk sums ----------------
// grid (NCH, BB, 3), 256 threads; chunk length CLEN=64.
__global__ __launch_bounds__(256)
void build_scan1_kernel(const float* __restrict__ ck,
                        const float* __restrict__ score_scale) {
    const int ch = blockIdx.x;
    const int b  = blockIdx.y;
    const int cs = blockIdx.z;
    const int tid = threadIdx.x;
    __shared__ float spw[KK][CLEN];
    const int l0 = ch * CLEN;
    const int t0 = b * LLEN + l0;

    // phase 1: threads 0..CLEN-1 compute pw for all 12 heads at their token
    if (tid < CLEN) {
        const int i = tid;
        const int l = l0 + i;
        const int t = t0 + i;
#pragma unroll
        for (int k = 0; k < KK; k++) {
            float s = 0.f;
#pragma unroll
            for (int j = 0; j < CKN; j++) {
                int ll = l - (CKN - 1) + j;
                if (ll >= 0)
                    s += g_zq[(size_t)(t - (CKN - 1) + j) * PW + MEM + k] * ck[j * 780 + MEM + k];
            }
            float lp = fminf(fmaxf(score_scale[k] * s, -20.f), 20.f);
            float pw = expf(lp - g_slope[k] * (float)(LLEN - 1 - l));
            spw[k][i] = pw;
            if (cs == 0) g_merged[(size_t)t * CHN + k] = pw;
        }
    }
    __syncthreads();
    if (cs == 0 && tid < KK) {
        float s = 0.f;
        for (int i = 0; i < CLEN; i++) s += spw[tid][i];
        g_part[(b * CHN + tid) * NCH + ch] = s;
    }

    // phase 2: kv channel c, rolling 4-tap window over CLEN tokens
    const int c = cs * 256 + tid;
    const int k = c >> 6;
    const float w0 = ck[0 * 780 + c], w1 = ck[1 * 780 + c];
    const float w2 = ck[2 * 780 + c], w3 = ck[3 * 780 + c];
    const float th = g_theta[c];
    float z0 = 0.f, z1 = 0.f, z2 = 0.f;
    if (l0 >= 3) {
        z0 = g_zq[(size_t)(t0 - 3) * PW + c];
        z1 = g_zq[(size_t)(t0 - 2) * PW + c];
        z2 = g_zq[(size_t)(t0 - 1) * PW + c];
    }
    float sum_re = 0.f, sum_im = 0.f;
    for (int i = 0; i < CLEN; i++) {
        const size_t t = (size_t)(t0 + i);
        float z3 = g_zq[t * PW + c];
        float kv = w0 * z0 + w1 * z1 + w2 * z2 + w3 * z3;
        float phi = tanhf(kv) * th;
        float sn, cn;
        sincosf(phi, &sn, &cn);
        float wgt = kv * spw[k][i];
        float re = wgt * cn, im = wgt * sn;
        g_merged[t * CHN + KK + c] = re;
        g_merged[t * CHN + KK + FLAT + c] = im;
        sum_re += re;
        sum_im += im;
        z0 = z1; z1 = z2; z2 = z3;
    }
    g_part[(b * CHN + KK + c) * NCH + ch] = sum_re;
    g_part[(b * CHN + KK + FLAT + c) * NCH + ch] = sum_im;
}

// ---------------- pass2: exclusive prefix over chunk sums ----------------
__global__ void scan_pass2() {
    int idx = blockIdx.x * 256 + threadIdx.x;
    if (idx >= BB * CHN) return;
    int base = idx * NCH;
    float off = 0.f;
#pragma unroll
    for (int i = 0; i < NCH; i++) {
        float v = g_part[base + i];
        g_part[base + i] = off;
        off += v;
    }
}

// ---------------- fused pass3 + combine: cumsum (registers) -> o (bf16 hi/lo) ----------------
// grid (NCH, BB, KK), 64 threads; chunk length CLEN=64, 1 den value/thread.
__global__ __launch_bounds__(64)
void scan3_combine_kernel(const float* __restrict__ norm_scale) {
    const int ch = blockIdx.x;
    const int b  = blockIdx.y;
    const int k  = blockIdx.z;
    const int l  = threadIdx.x;    // 0..63
    __shared__ float sinv[CLEN];
    __shared__ float wsum;
    const int t0 = b * LLEN + ch * CLEN;

    // inclusive scan of den over 64 tokens (1/thread, 2 warps)
    float v = g_merged[(size_t)(t0 + l) * CHN + k];
    float s = v;
#pragma unroll
    for (int d = 1; d < 32; d <<= 1) {
        float t = __shfl_up_sync(0xFFFFFFFFu, s, d);
        if ((l & 31) >= d) s += t;
    }
    if (l == 31) wsum = s;
    __syncthreads();
    float incl = g_part[(b * CHN + k) * NCH + ch] + s + ((l >= 32) ? wsum : 0.f);
    sinv[l] = 1.f / fmaxf(incl, 1e-4f);
    __syncthreads();

    const int hh = l;
    const int cre = KK + k * 64 + hh;
    const int cim = KK + FLAT + k * 64 + hh;
    float run_re = g_part[(b * CHN + cre) * NCH + ch];
    float run_im = g_part[(b * CHN + cim) * NCH + ch];
    const float ns = norm_scale[k * 64 + hh];
    const int kq = k >> 1;

#pragma unroll 4
    for (int i = 0; i < CLEN; i++) {
        const size_t t = (size_t)(t0 + i);
        run_re += g_merged[t * CHN + cre];
        run_im += g_merged[t * CHN + cim];
        float iv = sinv[i];
        float sre = run_re * iv;
        float sim = run_im * iv;
        float2 q2 = *(const float2*)(g_zq + t * PW + OFF_Q + kq * 128 + 2 * hh);
        float vre = (sre * q2.x + sim * q2.y) * ns;
        float vim = (sim * q2.x - sre * q2.y) * ns;
        size_t oidx = t * 1536 + k * 128 + hh;
        __nv_bfloat16 hb;
        hb = __float2bfloat16(vre);
        g_ohi[oidx] = hb;
        g_olo[oidx] = __float2bfloat16(vre - __bfloat162float(hb));
        hb = __float2bfloat16(vim);
        g_ohi[oidx + 64] = hb;
        g_olo[oidx + 64] = __float2bfloat16(vim - __bfloat162float(hb));
    }
}

// ---------------- host ----------------
static float* sym_addr(const void* sym) {
    void* p = nullptr;
    cudaGetSymbolAddress(&p, sym);
    return (float*)p;
}

extern "C" void kernel_launch(void* const* d_in, const int* in_sizes, int n_in,
                              void* d_out, int out_size) {
    const float* x        = (const float*)d_in[0];
    const float* W_mem    = (const float*)d_in[1];
    const float* conv_k   = (const float*)d_in[2];
    const float* W_q      = (const float*)d_in[3];
    const float* th_raw   = (const float*)d_in[4];
    const float* d_slopes = (const float*)d_in[5];
    const float* sc_scale = (const float*)d_in[6];
    const float* W_re     = (const float*)d_in[7];
    const float* W_im     = (const float*)d_in[8];
    const float* n_scale  = (const float*)d_in[9];
    const float* Wg       = (const float*)d_in[10];
    const float* bg       = (const float*)d_in[11];
    const float* W_down   = (const float*)d_in[12];
    const float* W_up     = (const float*)d_in[13];
    const float* hw       = (const float*)d_in[14];
    const float* W_out    = (const float*)d_in[15];
    float* out = (float*)d_out;

    float* pwcatT = sym_addr(g_wcatT);
    float* pwupT  = sym_addr(g_wupT);
    float* pwoutT = sym_addr(g_woutT);
    float* pxr    = sym_addr(g_xr);
    float* pzq    = sym_addr(g_zq);
    float* pya    = sym_addr(g_ya);

    static cudaStream_t s1;
    static cudaEvent_t evA, evC, evW;
    static int init_done = 0;
    if (!init_done) {
        cudaFuncSetAttribute(tf32_mma_gemm, cudaFuncAttributeMaxDynamicSharedMemorySize, GEMM_SMEM);
        cudaFuncSetAttribute(spec_up_mma_kernel, cudaFuncAttributeMaxDynamicSharedMemorySize, SPEC_SMEM);
        cudaStreamCreateWithFlags(&s1, cudaStreamNonBlocking);
        cudaEventCreateWithFlags(&evA, cudaEventDisableTiming);
        cudaEventCreateWithFlags(&evC, cudaEventDisableTiming);
        cudaEventCreateWithFlags(&evW, cudaEventDisableTiming);
        init_done = 1;
    }

    dim3 blk(256);
    const int MB = TOK / 128;   // 128 row-blocks
    const int NOROUND = 1 << 30;

    // ---- fork side stream: pack (needed by proj) first, then the rest of the prep ----
    cudaEventRecord(evA, 0);
    cudaStreamWaitEvent(s1, evA, 0);
    pack_wcatT_kernel<<<(PW * DD + 255) / 256, blk, 0, s1>>>(W_mem, W_q, Wg, W_down);
    cudaEventRecord(evW, s1);
    precomp_kernel<<<1, 768, 0, s1>>>(th_raw, d_slopes);
    transpose_tiled_kernel<<<dim3(LAT / 32, 4608 / 32), dim3(32, 8), 0, s1>>>(W_up, pwupT, LAT, 4608);
    transpose_tiled_kernel<<<dim3(2304 / 32, DD / 32), dim3(32, 8), 0, s1>>>(W_out, pwoutT, 2304, DD);
    spec_bt_kernel<<<(KK * DSW * 128 + 255) / 256, blk, 0, s1>>>(W_re, W_im);
    cudaEventRecord(evC, s1);

    // ---- main: x rounding (overlaps pack), then projection GEMM ----
    round_copy_kernel<<<(TOK * DD / 4 + 255) / 256, blk>>>(x, pxr, TOK * DD / 4);
    cudaStreamWaitEvent(0, evW, 0);
    tf32_mma_gemm<<<dim3(14, MB), blk, GEMM_SMEM>>>(pxr, pwcatT, pzq, PW, DD, DD, PW, OFF_D);

    // ---- main: fused merged+pass1, pass2, scan3 (needs precomp from side) ----
    cudaStreamWaitEvent(0, evC, 0);
    build_scan1_kernel<<<dim3(NCH, BB, 3), blk>>>(conv_k, sc_scale);
    {
        int n2 = BB * CHN;
        scan_pass2<<<(n2 + 255) / 256, blk>>>();
    }
    scan3_combine_kernel<<<dim3(NCH, BB, KK), 64>>>(n_scale);

    // ---- fused up+spec+silu GEMM -> ya ----
    spec_up_mma_kernel<<<dim3(3, MB, KK), blk, SPEC_SMEM>>>(bg, hw);

    // ---- final projection ----
    tf32_mma_gemm<<<dim3(6, MB), blk, GEMM_SMEM>>>(pya, pwoutT, out, DD, 2304, 2304, DD, NOROUND);
}